// round 2
// baseline (speedup 1.0000x reference)
#include <cuda_runtime.h>
#include <math.h>

// MonotonicNN (UMNN) forward:
//   out[b] = h[b] + 0.5*x[b] * sum_s ccw[s] * ( elu(MLP([x[b]*t_s, h[b]])) + 1 )
// MLP: (2->128 relu) (128->128 relu) (128->128 relu) (128->1 elu)
// Flattened as N = 51*16384 rows, s-major. Pass 1: per-(s, 128-row) CTA computes
// dz into __device__ scratch. Pass 2: tiny weighted reduction over s.

#define BATCH   16384
#define NS      51
#define HID     128
#define TM      128          // batch rows per CTA
#define ASTRIDE 132          // padded activation row (floats)
#define NTHR    256

__device__ float g_dz[NS * BATCH];
__device__ float g_ccw[NS];
__device__ float g_t[NS];

#define PI_D 3.14159265358979323846

// ---------- packed f32x2 helpers (Blackwell FFMA2) ----------
__device__ __forceinline__ unsigned long long pack2(float lo, float hi) {
    unsigned long long r;
    asm("mov.b64 %0, {%1, %2};" : "=l"(r) : "f"(lo), "f"(hi));
    return r;
}
__device__ __forceinline__ unsigned long long ffma2(unsigned long long a,
                                                    unsigned long long b,
                                                    unsigned long long c) {
    unsigned long long d;
    asm("fma.rn.f32x2 %0, %1, %2, %3;" : "=l"(d) : "l"(a), "l"(b), "l"(c));
    return d;
}
__device__ __forceinline__ void unpack2(unsigned long long v, float& lo, float& hi) {
    asm("mov.b64 {%0, %1}, %2;" : "=f"(lo), "=f"(hi) : "l"(v));
}

// ---------- init: Clenshaw-Curtis weights (fp64, matches numpy) ----------
__global__ void cc_init_kernel() {
    int j = threadIdx.x;
    if (j < NS) {
        const int nb = NS - 1;  // 50
        double acc = 0.0;
        for (int i = 0; i <= nb; i++) {
            double Wi;
            if (i == 0)        Wi = 1.0;
            else if (i & 1)    Wi = 0.0;
            else               Wi = 2.0 / (1.0 - (double)i * (double)i);
            acc += cos((double)i * (double)j * PI_D / (double)nb) * Wi;
        }
        acc *= 2.0 / (double)nb;
        if (j == 0 || j == nb) acc *= 0.5;
        g_ccw[j] = (float)acc;
        g_t[j]   = (float)((cos((double)j * PI_D / (double)nb) + 1.0) * 0.5);
    }
}

// ---------- pass 1: MLP over one (s, 128-row) tile ----------
__global__ void __launch_bounds__(NTHR, 1)
mlp_main_kernel(const float* __restrict__ x,  const float* __restrict__ h,
                const float* __restrict__ w1, const float* __restrict__ b1,
                const float* __restrict__ w2, const float* __restrict__ b2,
                const float* __restrict__ w3, const float* __restrict__ b3,
                const float* __restrict__ w4, const float* __restrict__ b4) {
    extern __shared__ float smem[];
    float* sW2 = smem;                       // [128][128]
    float* sW3 = smem + HID * HID;           // [128][128]
    float* sA  = smem + 2 * HID * HID;       // [128][ASTRIDE]

    const int tid   = threadIdx.x;
    const int bbase = blockIdx.x * TM;
    const int s     = blockIdx.y;

    // load both weight matrices to smem (float4, coalesced)
    {
        const float4* g2 = (const float4*)w2;
        const float4* g3 = (const float4*)w3;
        float4* s2 = (float4*)sW2;
        float4* s3 = (float4*)sW3;
        for (int i = tid; i < HID * HID / 4; i += NTHR) {
            s2[i] = g2[i];
            s3[i] = g3[i];
        }
    }

    // layer 1: sA[m][k] = relu(x[b]*t_s*w1[0][k] + h[b]*w1[1][k] + b1[k])
    const float tS = g_t[s];
    for (int e = tid; e < TM * HID; e += NTHR) {
        int m = e >> 7;
        int k = e & (HID - 1);
        float xv = x[bbase + m] * tS;
        float hv = h[bbase + m];
        float v  = fmaf(xv, w1[k], fmaf(hv, w1[HID + k], b1[k]));
        sA[m * ASTRIDE + k] = fmaxf(v, 0.0f);
    }
    __syncthreads();

    // thread tile: tx in [0,32) -> 4 output cols (jbase..jbase+3)
    //              ty in [0,8)  -> 16 rows (mbase..mbase+15)
    const int tx = tid & 31;
    const int ty = tid >> 5;
    const int jbase = tx * 4;
    const int mbase = ty * 16;

    for (int layer = 0; layer < 2; layer++) {
        const float* sW   = layer ? sW3 : sW2;
        const float* bias = layer ? b3  : b2;

        unsigned long long acc[32];  // [rm=16][pair=2]
        #pragma unroll
        for (int i = 0; i < 32; i++) acc[i] = 0ULL;

        for (int k = 0; k < HID; k += 4) {
            // weight pairs for 4 consecutive k, 4 cols each: 2 f32x2 per k
            unsigned long long wf[4][2];
            #pragma unroll
            for (int kk = 0; kk < 4; kk++) {
                ulonglong2 wv = *(const ulonglong2*)(sW + (k + kk) * HID + jbase);
                wf[kk][0] = wv.x;  // cols jbase, jbase+1
                wf[kk][1] = wv.y;  // cols jbase+2, jbase+3
            }
            #pragma unroll
            for (int rm = 0; rm < 16; rm++) {
                float4 a4 = *(const float4*)&sA[(mbase + rm) * ASTRIDE + k];  // warp-broadcast
                unsigned long long ap;
                ap = pack2(a4.x, a4.x);
                acc[rm*2+0] = ffma2(ap, wf[0][0], acc[rm*2+0]);
                acc[rm*2+1] = ffma2(ap, wf[0][1], acc[rm*2+1]);
                ap = pack2(a4.y, a4.y);
                acc[rm*2+0] = ffma2(ap, wf[1][0], acc[rm*2+0]);
                acc[rm*2+1] = ffma2(ap, wf[1][1], acc[rm*2+1]);
                ap = pack2(a4.z, a4.z);
                acc[rm*2+0] = ffma2(ap, wf[2][0], acc[rm*2+0]);
                acc[rm*2+1] = ffma2(ap, wf[2][1], acc[rm*2+1]);
                ap = pack2(a4.w, a4.w);
                acc[rm*2+0] = ffma2(ap, wf[3][0], acc[rm*2+0]);
                acc[rm*2+1] = ffma2(ap, wf[3][1], acc[rm*2+1]);
            }
        }
        __syncthreads();  // all reads of sA done before overwrite

        float bj0 = bias[jbase + 0];
        float bj1 = bias[jbase + 1];
        float bj2 = bias[jbase + 2];
        float bj3 = bias[jbase + 3];
        #pragma unroll
        for (int rm = 0; rm < 16; rm++) {
            float v0, v1, v2, v3;
            unpack2(acc[rm*2+0], v0, v1);
            unpack2(acc[rm*2+1], v2, v3);
            v0 = fmaxf(v0 + bj0, 0.0f);
            v1 = fmaxf(v1 + bj1, 0.0f);
            v2 = fmaxf(v2 + bj2, 0.0f);
            v3 = fmaxf(v3 + bj3, 0.0f);
            float* dst = &sA[(mbase + rm) * ASTRIDE + jbase];
            *(float2*)(dst)     = make_float2(v0, v1);
            *(float2*)(dst + 2) = make_float2(v2, v3);
        }
        __syncthreads();
    }

    // layer 4 + elu + 1 -> dz scratch
    if (tid < TM) {
        const int m = tid;
        float acc4x = 0.f, acc4y = 0.f, acc4z = 0.f, acc4w = 0.f;
        const float4* arow = (const float4*)&sA[m * ASTRIDE];
        const float4* w4v  = (const float4*)w4;
        #pragma unroll 8
        for (int q = 0; q < HID / 4; q++) {
            float4 a4 = arow[q];
            float4 w4q = w4v[q];
            acc4x = fmaf(a4.x, w4q.x, acc4x);
            acc4y = fmaf(a4.y, w4q.y, acc4y);
            acc4z = fmaf(a4.z, w4q.z, acc4z);
            acc4w = fmaf(a4.w, w4q.w, acc4w);
        }
        float v = (acc4x + acc4y) + (acc4z + acc4w) + b4[0];
        float e = (v > 0.0f) ? v : expm1f(v);   // elu
        g_dz[s * BATCH + bbase + m] = e + 1.0f;
    }
}

// ---------- pass 2: weighted reduction over s ----------
__global__ void reduce_kernel(const float* __restrict__ x,
                              const float* __restrict__ h,
                              float* __restrict__ out) {
    int b = blockIdx.x * blockDim.x + threadIdx.x;
    if (b < BATCH) {
        float acc = 0.0f;
        #pragma unroll
        for (int s = 0; s < NS; s++)
            acc = fmaf(g_ccw[s], g_dz[s * BATCH + b], acc);
        out[b] = fmaf(acc, 0.5f * x[b], h[b]);
    }
}

extern "C" void kernel_launch(void* const* d_in, const int* in_sizes, int n_in,
                              void* d_out, int out_size) {
    const float* x  = (const float*)d_in[0];
    const float* h  = (const float*)d_in[1];
    const float* w1 = (const float*)d_in[2];
    const float* b1 = (const float*)d_in[3];
    const float* w2 = (const float*)d_in[4];
    const float* b2 = (const float*)d_in[5];
    const float* w3 = (const float*)d_in[6];
    const float* b3 = (const float*)d_in[7];
    const float* w4 = (const float*)d_in[8];
    const float* b4 = (const float*)d_in[9];
    float* out = (float*)d_out;

    const int smem_bytes = (2 * HID * HID + TM * ASTRIDE) * (int)sizeof(float);
    static int attr_set = 0;
    if (!attr_set) {
        cudaFuncSetAttribute(mlp_main_kernel,
                             cudaFuncAttributeMaxDynamicSharedMemorySize, smem_bytes);
        attr_set = 1;
    }

    cc_init_kernel<<<1, 64>>>();
    dim3 grid(BATCH / TM, NS);
    mlp_main_kernel<<<grid, NTHR, smem_bytes>>>(x, h, w1, b1, w2, b2, w3, b3, w4, b4);
    reduce_kernel<<<BATCH / 256, 256>>>(x, h, out);
}

// round 3
// speedup vs baseline: 1.0979x; 1.0979x over previous
#include <cuda_runtime.h>
#include <math.h>

// MonotonicNN (UMNN) forward:
//   out[b] = h[b] + 0.5*x[b] * sum_s ccw[s] * ( elu(MLP([x[b]*t_s, h[b]])) + 1 )
// MLP: (2->128 relu) (128->128 relu) (128->128 relu) (128->1 elu)
// Pass 1 (grid 128x51, 512 thr): per-(s, 128-row) CTA computes dz -> scratch.
// Pass 2: weighted reduction over s (computes CC weights in-block via cospif).

#define BATCH   16384
#define NS      51
#define NB      50
#define HID     128
#define TM      128          // batch rows per CTA
#define ASTRIDE 132          // padded activation row (floats)
#define NTHR    512

__device__ float g_dz[NS * BATCH];

// ---------- packed f32x2 helpers (Blackwell FFMA2) ----------
__device__ __forceinline__ unsigned long long pack2(float lo, float hi) {
    unsigned long long r;
    asm("mov.b64 %0, {%1, %2};" : "=l"(r) : "f"(lo), "f"(hi));
    return r;
}
__device__ __forceinline__ unsigned long long ffma2(unsigned long long a,
                                                    unsigned long long b,
                                                    unsigned long long c) {
    unsigned long long d;
    asm("fma.rn.f32x2 %0, %1, %2, %3;" : "=l"(d) : "l"(a), "l"(b), "l"(c));
    return d;
}
__device__ __forceinline__ void unpack2(unsigned long long v, float& lo, float& hi) {
    asm("mov.b64 {%0, %1}, %2;" : "=f"(lo), "=f"(hi) : "l"(v));
}

// ---------- pass 1: MLP over one (s, 128-row) tile ----------
__global__ void __launch_bounds__(NTHR, 1)
mlp_main_kernel(const float* __restrict__ x,  const float* __restrict__ h,
                const float* __restrict__ w1, const float* __restrict__ b1,
                const float* __restrict__ w2, const float* __restrict__ b2,
                const float* __restrict__ w3, const float* __restrict__ b3,
                const float* __restrict__ w4, const float* __restrict__ b4) {
    extern __shared__ float smem[];
    float* sW2 = smem;                         // [128][128]
    float* sW3 = smem + HID * HID;             // [128][128]
    float* sA  = smem + 2 * HID * HID;         // [128][ASTRIDE]
    float* sW4 = smem + 2 * HID * HID + TM * ASTRIDE;  // [128]

    const int tid   = threadIdx.x;
    const int bbase = blockIdx.x * TM;
    const int s     = blockIdx.y;

    // stage weights to smem (float4, coalesced)
    {
        const float4* g2 = (const float4*)w2;
        const float4* g3 = (const float4*)w3;
        float4* s2 = (float4*)sW2;
        float4* s3 = (float4*)sW3;
        for (int i = tid; i < HID * HID / 4; i += NTHR) {
            s2[i] = g2[i];
            s3[i] = g3[i];
        }
        if (tid < HID) sW4[tid] = w4[tid];
    }

    // quadrature abscissa for this s (fp32 cospif, ~2ulp vs fp64 ref)
    const float tS = (cospif((float)s / (float)NB) + 1.0f) * 0.5f;

    // layer 1: sA[m][k] = relu(x*t_s*w1[0][k] + h*w1[1][k] + b1[k])
    for (int e = tid; e < TM * HID; e += NTHR) {
        int m = e >> 7;
        int k = e & (HID - 1);
        float xv = x[bbase + m] * tS;
        float hv = h[bbase + m];
        float v  = fmaf(xv, w1[k], fmaf(hv, w1[HID + k], b1[k]));
        sA[m * ASTRIDE + k] = fmaxf(v, 0.0f);
    }
    __syncthreads();

    // thread tile: tx in [0,32) -> 4 cols, ty in [0,16) -> 8 rows
    const int tx = tid & 31;
    const int ty = tid >> 5;
    const int jbase = tx * 4;
    const int mbase = ty * 8;

    for (int layer = 0; layer < 2; layer++) {
        const float* sW   = layer ? sW3 : sW2;
        const float* bias = layer ? b3  : b2;

        unsigned long long acc[16];  // [rm=8][pair=2]
        #pragma unroll
        for (int i = 0; i < 16; i++) acc[i] = 0ULL;

        for (int k = 0; k < HID; k += 4) {
            unsigned long long wf[4][2];
            #pragma unroll
            for (int kk = 0; kk < 4; kk++) {
                ulonglong2 wv = *(const ulonglong2*)(sW + (k + kk) * HID + jbase);
                wf[kk][0] = wv.x;  // cols jbase, jbase+1
                wf[kk][1] = wv.y;  // cols jbase+2, jbase+3
            }
            #pragma unroll
            for (int rm = 0; rm < 8; rm++) {
                float4 a4 = *(const float4*)&sA[(mbase + rm) * ASTRIDE + k];  // warp-broadcast
                unsigned long long ap;
                ap = pack2(a4.x, a4.x);
                acc[rm*2+0] = ffma2(ap, wf[0][0], acc[rm*2+0]);
                acc[rm*2+1] = ffma2(ap, wf[0][1], acc[rm*2+1]);
                ap = pack2(a4.y, a4.y);
                acc[rm*2+0] = ffma2(ap, wf[1][0], acc[rm*2+0]);
                acc[rm*2+1] = ffma2(ap, wf[1][1], acc[rm*2+1]);
                ap = pack2(a4.z, a4.z);
                acc[rm*2+0] = ffma2(ap, wf[2][0], acc[rm*2+0]);
                acc[rm*2+1] = ffma2(ap, wf[2][1], acc[rm*2+1]);
                ap = pack2(a4.w, a4.w);
                acc[rm*2+0] = ffma2(ap, wf[3][0], acc[rm*2+0]);
                acc[rm*2+1] = ffma2(ap, wf[3][1], acc[rm*2+1]);
            }
        }
        __syncthreads();  // all sA reads complete before overwrite

        float bj0 = bias[jbase + 0];
        float bj1 = bias[jbase + 1];
        float bj2 = bias[jbase + 2];
        float bj3 = bias[jbase + 3];
        #pragma unroll
        for (int rm = 0; rm < 8; rm++) {
            float v0, v1, v2, v3;
            unpack2(acc[rm*2+0], v0, v1);
            unpack2(acc[rm*2+1], v2, v3);
            v0 = fmaxf(v0 + bj0, 0.0f);
            v1 = fmaxf(v1 + bj1, 0.0f);
            v2 = fmaxf(v2 + bj2, 0.0f);
            v3 = fmaxf(v3 + bj3, 0.0f);
            float* dst = &sA[(mbase + rm) * ASTRIDE + jbase];
            *(float2*)(dst)     = make_float2(v0, v1);
            *(float2*)(dst + 2) = make_float2(v2, v3);
        }
        __syncthreads();
    }

    // layer 4 + elu + 1 -> dz. 4 threads per row, 32 k each, shfl reduce.
    {
        const int m = tid >> 2;        // 0..127
        const int q = tid & 3;         // 0..3
        const float4* arow = (const float4*)&sA[m * ASTRIDE + q * 32];
        const float4* wrow = (const float4*)&sW4[q * 32];
        float ax = 0.f, ay = 0.f, az = 0.f, aw = 0.f;
        #pragma unroll
        for (int i = 0; i < 8; i++) {
            float4 a4 = arow[i];
            float4 wv = wrow[i];
            ax = fmaf(a4.x, wv.x, ax);
            ay = fmaf(a4.y, wv.y, ay);
            az = fmaf(a4.z, wv.z, az);
            aw = fmaf(a4.w, wv.w, aw);
        }
        float p = (ax + ay) + (az + aw);
        p += __shfl_xor_sync(0xFFFFFFFFu, p, 1);
        p += __shfl_xor_sync(0xFFFFFFFFu, p, 2);
        if (q == 0) {
            float v = p + b4[0];
            float e = (v > 0.0f) ? v : expm1f(v);   // elu
            g_dz[s * BATCH + bbase + m] = e + 1.0f;
        }
    }
}

// ---------- pass 2: weighted reduction over s (ccw computed in-block) ----------
__global__ void __launch_bounds__(256)
reduce_kernel(const float* __restrict__ x, const float* __restrict__ h,
              float* __restrict__ out) {
    __shared__ float sccw[NS];
    const int tid = threadIdx.x;
    if (tid < NS) {
        // Clenshaw-Curtis weight j = (2/nb) * sum_i cos(pi*i*j/nb) * W[i], edge-halved
        float acc = 0.0f;
        #pragma unroll 1
        for (int i = 0; i <= NB; i++) {
            float Wi;
            if (i == 0)      Wi = 1.0f;
            else if (i & 1)  Wi = 0.0f;
            else             Wi = 2.0f / (1.0f - (float)i * (float)i);
            acc = fmaf(cospif((float)(i * tid) / (float)NB), Wi, acc);
        }
        acc *= 2.0f / (float)NB;
        if (tid == 0 || tid == NB) acc *= 0.5f;
        sccw[tid] = acc;
    }
    __syncthreads();

    int b = blockIdx.x * blockDim.x + tid;
    float acc = 0.0f;
    #pragma unroll
    for (int s = 0; s < NS; s++)
        acc = fmaf(sccw[s], g_dz[s * BATCH + b], acc);
    out[b] = fmaf(acc, 0.5f * x[b], h[b]);
}

extern "C" void kernel_launch(void* const* d_in, const int* in_sizes, int n_in,
                              void* d_out, int out_size) {
    const float* x  = (const float*)d_in[0];
    const float* h  = (const float*)d_in[1];
    const float* w1 = (const float*)d_in[2];
    const float* b1 = (const float*)d_in[3];
    const float* w2 = (const float*)d_in[4];
    const float* b2 = (const float*)d_in[5];
    const float* w3 = (const float*)d_in[6];
    const float* b3 = (const float*)d_in[7];
    const float* w4 = (const float*)d_in[8];
    const float* b4 = (const float*)d_in[9];
    float* out = (float*)d_out;

    const int smem_bytes = (2 * HID * HID + TM * ASTRIDE + HID) * (int)sizeof(float);
    static int attr_set = 0;
    if (!attr_set) {
        cudaFuncSetAttribute(mlp_main_kernel,
                             cudaFuncAttributeMaxDynamicSharedMemorySize, smem_bytes);
        attr_set = 1;
    }

    dim3 grid(BATCH / TM, NS);
    mlp_main_kernel<<<grid, NTHR, smem_bytes>>>(x, h, w1, b1, w2, b2, w3, b3, w4, b4);
    reduce_kernel<<<BATCH / 256, 256>>>(x, h, out);
}

// round 5
// speedup vs baseline: 2.8476x; 2.5937x over previous
#include <cuda_runtime.h>
#include <cuda_bf16.h>
#include <math.h>
#include <stdint.h>

// MonotonicNN via mma.sync (HMMA) split-bf16 3-term GEMMs.
// Grid: 128 CTAs x 512 thr. CTA owns 128 batch rows, loops 51 quad points.
// Warp w: m-strip (w&7)*16, n-half (w>>3)*64 -> 8 m16n8 accum tiles.
// L1 fused into L2 mainloop (fragments built in registers).
// L2->L3 via smem bf16 hi/lo activation tiles (ldmatrix), rows padded to 272B.

#define NTHR  512
#define TM    128
#define NS    51
#define NB    50
#define BATCH 16384
#define HID   128
#define ASTR  136              // padded row length (bf16 elems) = 272 B

// smem byte offsets
#define TILE_B   (128 * ASTR * 2)      // 34816
#define OFF_W2HI 0
#define OFF_W2LO (1 * TILE_B)
#define OFF_W3HI (2 * TILE_B)
#define OFF_W3LO (3 * TILE_B)
#define OFF_AHI  (4 * TILE_B)
#define OFF_ALO  (5 * TILE_B)
#define OFF_MISC (6 * TILE_B)          // 208896
// float-indexed misc: [0,256) W1 | [256,384) B1 | [384,512) B2 | [512,640) B3
// [640,768) W4 | [768,896) X | [896,1024) H | [1024,1088) CCW | [1088,1344) PART | [1344] b4
#define SMEM_TOTAL (OFF_MISC + 1360 * 4)

__device__ __forceinline__ void mma_bf16(float* c, const uint32_t* a,
                                         uint32_t b0, uint32_t b1) {
    asm volatile(
        "mma.sync.aligned.m16n8k16.row.col.f32.bf16.bf16.f32 "
        "{%0,%1,%2,%3}, {%4,%5,%6,%7}, {%8,%9}, {%0,%1,%2,%3};"
        : "+f"(c[0]), "+f"(c[1]), "+f"(c[2]), "+f"(c[3])
        : "r"(a[0]), "r"(a[1]), "r"(a[2]), "r"(a[3]), "r"(b0), "r"(b1));
}

#define LDSM_X4(r, addr) \
    asm volatile("ldmatrix.sync.aligned.m8n8.x4.shared.b16 {%0,%1,%2,%3}, [%4];" \
        : "=r"((r)[0]), "=r"((r)[1]), "=r"((r)[2]), "=r"((r)[3]) : "r"(addr))

__device__ __forceinline__ uint32_t smem_to_u32(const void* p) {
    uint32_t a;
    asm("{ .reg .u64 t; cvta.to.shared.u64 t, %1; cvt.u32.u64 %0, t; }" : "=r"(a) : "l"(p));
    return a;
}

// split fp32 pair (v0=even elem, v1=odd) -> packed bf16x2 hi and lo (v0 in low half)
__device__ __forceinline__ void split_pack(float v0, float v1, uint32_t& hi, uint32_t& lo) {
    asm("cvt.rn.bf16x2.f32 %0, %1, %2;" : "=r"(hi) : "f"(v1), "f"(v0));
    float h0 = __uint_as_float(hi << 16);
    float h1 = __uint_as_float(hi & 0xFFFF0000u);
    float l0 = v0 - h0;
    float l1 = v1 - h1;
    asm("cvt.rn.bf16x2.f32 %0, %1, %2;" : "=r"(lo) : "f"(l1), "f"(l0));
}

__global__ void __launch_bounds__(NTHR, 1)
monnn_kernel(const float* __restrict__ x,  const float* __restrict__ h,
             const float* __restrict__ w1, const float* __restrict__ b1,
             const float* __restrict__ w2, const float* __restrict__ b2,
             const float* __restrict__ w3, const float* __restrict__ b3,
             const float* __restrict__ w4, const float* __restrict__ b4,
             float* __restrict__ out) {
    extern __shared__ char smem[];
    float* FM   = (float*)(smem + OFF_MISC);
    float* sW1  = FM;          float* sB1 = FM + 256;
    float* sB2  = FM + 384;    float* sB3 = FM + 512;
    float* sW4  = FM + 640;    float* sX  = FM + 768;
    float* sH   = FM + 896;    float* sCCW = FM + 1024;
    float* sPART = FM + 1088;  // [128][2]

    const int tid  = threadIdx.x;
    const int wid  = tid >> 5;
    const int lane = tid & 31;
    const int mbase = (wid & 7) * 16;     // warp m-strip
    const int nh    = wid >> 3;           // n-half 0/1
    const int nbase = nh * 64;
    const int bbase = blockIdx.x * TM;

    // ---- prologue: misc params ----
    for (int i = tid; i < 256; i += NTHR) sW1[i] = w1[i];
    if (tid < 128) {
        sB1[tid] = b1[tid]; sB2[tid] = b2[tid]; sB3[tid] = b3[tid];
        sW4[tid] = w4[tid];
        sX[tid] = x[bbase + tid]; sH[tid] = h[bbase + tid];
    }
    if (tid < NS) {  // Clenshaw-Curtis weights (fp32 cospif, validated R3)
        float acc = 0.0f;
        #pragma unroll 1
        for (int i = 0; i <= NB; i++) {
            float Wi = (i == 0) ? 1.0f : ((i & 1) ? 0.0f : 2.0f / (1.0f - (float)(i * i)));
            acc = fmaf(cospif((float)(i * tid) / (float)NB), Wi, acc);
        }
        acc *= 2.0f / (float)NB;
        if (tid == 0 || tid == NB) acc *= 0.5f;
        sCCW[tid] = acc;
    }
    if (tid == 0) FM[1344] = b4[0];

    // ---- prologue: W2,W3 -> transposed split-bf16 tiles Wt[j][k] ----
    for (int i = tid; i < HID * HID; i += NTHR) {
        int k = i >> 7, j = i & 127;       // w[k][j] row-major
        int o = j * ASTR + k;
        float v = w2[i];
        __nv_bfloat16 hb = __float2bfloat16(v);
        ((__nv_bfloat16*)(smem + OFF_W2HI))[o] = hb;
        ((__nv_bfloat16*)(smem + OFF_W2LO))[o] = __float2bfloat16(v - __bfloat162float(hb));
        v = w3[i];
        hb = __float2bfloat16(v);
        ((__nv_bfloat16*)(smem + OFF_W3HI))[o] = hb;
        ((__nv_bfloat16*)(smem + OFF_W3LO))[o] = __float2bfloat16(v - __bfloat162float(hb));
    }
    __syncthreads();

    // ---- per-thread constants ----
    const int r0 = mbase + (lane >> 2);        // c/a-frag row 0
    const int r1 = r0 + 8;                     // c/a-frag row 1
    const int kq = (lane & 3) * 2;             // frag col/k pair base
    const float xm0 = sX[r0], xm1 = sX[r1];
    const float hm0 = sH[r0], hm1 = sH[r1];
    const float b4v = FM[1344];
    // ldmatrix per-lane row pointer offset within an A tile
    const int lm_row = mbase + (lane & 7) + ((lane >> 3) & 1) * 8;
    const uint32_t lm_off = (uint32_t)(lm_row * ASTR * 2 + ((lane >> 4) * 8) * 2);
    const uint32_t sb = smem_to_u32(smem);
    // B operand per-lane base: n = nbase + 8t + lane/4, k pair = kq (+8j) (+16ks)
    const uint32_t bn_off = (uint32_t)((nbase + (lane >> 2)) * ASTR * 2 + kq * 2);

    float zacc = 0.0f;

    for (int s = 0; s < NS; s++) {
        const float tS = (cospif((float)s / (float)NB) + 1.0f) * 0.5f;
        const float xs0 = xm0 * tS, xs1 = xm1 * tS;

        // ================= layer 2 (L1 fused, A frags in registers) =================
        float acc[8][4];
        #pragma unroll
        for (int t = 0; t < 8; t++)
            #pragma unroll
            for (int q = 0; q < 4; q++) acc[t][q] = 0.0f;

        #pragma unroll 1
        for (int ks = 0; ks < 8; ks++) {
            uint32_t ahi[4], alo[4];
            #pragma unroll
            for (int j = 0; j < 2; j++) {
                int k = ks * 16 + kq + 8 * j;
                float2 wa = *(const float2*)&sW1[k];
                float2 wb = *(const float2*)&sW1[128 + k];
                float2 bb = *(const float2*)&sB1[k];
                float v00 = fmaxf(fmaf(xs0, wa.x, fmaf(hm0, wb.x, bb.x)), 0.0f);
                float v01 = fmaxf(fmaf(xs0, wa.y, fmaf(hm0, wb.y, bb.y)), 0.0f);
                float v10 = fmaxf(fmaf(xs1, wa.x, fmaf(hm1, wb.x, bb.x)), 0.0f);
                float v11 = fmaxf(fmaf(xs1, wa.y, fmaf(hm1, wb.y, bb.y)), 0.0f);
                split_pack(v00, v01, ahi[2 * j],     alo[2 * j]);
                split_pack(v10, v11, ahi[2 * j + 1], alo[2 * j + 1]);
            }
            const uint32_t whi = sb + OFF_W2HI + bn_off + ks * 32;
            const uint32_t wlo = sb + OFF_W2LO + bn_off + ks * 32;
            #pragma unroll
            for (int t = 0; t < 8; t++) {
                uint32_t bo = (uint32_t)(t * (8 * ASTR * 2));
                uint32_t bh0 = *(const uint32_t*)(smem + (whi - sb) + bo);
                uint32_t bh1 = *(const uint32_t*)(smem + (whi - sb) + bo + 16);
                uint32_t bl0 = *(const uint32_t*)(smem + (wlo - sb) + bo);
                uint32_t bl1 = *(const uint32_t*)(smem + (wlo - sb) + bo + 16);
                mma_bf16(acc[t], ahi, bh0, bh1);
                mma_bf16(acc[t], alo, bh0, bh1);
                mma_bf16(acc[t], ahi, bl0, bl1);
            }
        }

        __syncthreads();   // prev-iter L3 A-reads + sPART combine done

        // ---- L2 epilogue: relu(D+b2) -> split-bf16 A tiles ----
        #pragma unroll
        for (int t = 0; t < 8; t++) {
            int n0 = nbase + 8 * t + kq;
            float2 b2v = *(const float2*)&sB2[n0];
            float v0 = fmaxf(acc[t][0] + b2v.x, 0.0f);
            float v1 = fmaxf(acc[t][1] + b2v.y, 0.0f);
            float v2 = fmaxf(acc[t][2] + b2v.x, 0.0f);
            float v3 = fmaxf(acc[t][3] + b2v.y, 0.0f);
            uint32_t hi, lo;
            split_pack(v0, v1, hi, lo);
            *(uint32_t*)(smem + OFF_AHI + r0 * ASTR * 2 + n0 * 2) = hi;
            *(uint32_t*)(smem + OFF_ALO + r0 * ASTR * 2 + n0 * 2) = lo;
            split_pack(v2, v3, hi, lo);
            *(uint32_t*)(smem + OFF_AHI + r1 * ASTR * 2 + n0 * 2) = hi;
            *(uint32_t*)(smem + OFF_ALO + r1 * ASTR * 2 + n0 * 2) = lo;
        }
        __syncthreads();

        // ================= layer 3 (A via ldmatrix) =================
        #pragma unroll
        for (int t = 0; t < 8; t++)
            #pragma unroll
            for (int q = 0; q < 4; q++) acc[t][q] = 0.0f;

        #pragma unroll 1
        for (int ks = 0; ks < 8; ks++) {
            uint32_t ahi[4], alo[4];
            LDSM_X4(ahi, sb + OFF_AHI + lm_off + ks * 32);
            LDSM_X4(alo, sb + OFF_ALO + lm_off + ks * 32);
            const uint32_t whi = OFF_W3HI + bn_off + ks * 32;
            const uint32_t wlo = OFF_W3LO + bn_off + ks * 32;
            #pragma unroll
            for (int t = 0; t < 8; t++) {
                uint32_t bo = (uint32_t)(t * (8 * ASTR * 2));
                uint32_t bh0 = *(const uint32_t*)(smem + whi + bo);
                uint32_t bh1 = *(const uint32_t*)(smem + whi + bo + 16);
                uint32_t bl0 = *(const uint32_t*)(smem + wlo + bo);
                uint32_t bl1 = *(const uint32_t*)(smem + wlo + bo + 16);
                mma_bf16(acc[t], ahi, bh0, bh1);
                mma_bf16(acc[t], alo, bh0, bh1);
                mma_bf16(acc[t], ahi, bl0, bl1);
            }
        }

        // ---- layer 4: dot(relu(D+b3), w4) ----
        float p0 = 0.0f, p1 = 0.0f;
        #pragma unroll
        for (int t = 0; t < 8; t++) {
            int n0 = nbase + 8 * t + kq;
            float2 b3v = *(const float2*)&sB3[n0];
            float2 w4v = *(const float2*)&sW4[n0];
            p0 = fmaf(fmaxf(acc[t][0] + b3v.x, 0.0f), w4v.x, p0);
            p0 = fmaf(fmaxf(acc[t][1] + b3v.y, 0.0f), w4v.y, p0);
            p1 = fmaf(fmaxf(acc[t][2] + b3v.x, 0.0f), w4v.x, p1);
            p1 = fmaf(fmaxf(acc[t][3] + b3v.y, 0.0f), w4v.y, p1);
        }
        p0 += __shfl_xor_sync(0xFFFFFFFFu, p0, 1);
        p0 += __shfl_xor_sync(0xFFFFFFFFu, p0, 2);
        p1 += __shfl_xor_sync(0xFFFFFFFFu, p1, 1);
        p1 += __shfl_xor_sync(0xFFFFFFFFu, p1, 2);
        if ((lane & 3) == 0) {
            sPART[r0 * 2 + nh] = p0;
            sPART[r1 * 2 + nh] = p1;
        }
        __syncthreads();

        if (tid < 128) {
            float v = sPART[tid * 2] + sPART[tid * 2 + 1] + b4v;
            float e = (v > 0.0f) ? v : expm1f(v);   // elu
            zacc = fmaf(sCCW[s], e + 1.0f, zacc);
        }
    }

    if (tid < 128)
        out[bbase + tid] = fmaf(zacc, 0.5f * sX[tid], sH[tid]);
}

extern "C" void kernel_launch(void* const* d_in, const int* in_sizes, int n_in,
                              void* d_out, int out_size) {
    const float* x  = (const float*)d_in[0];
    const float* h  = (const float*)d_in[1];
    const float* w1 = (const float*)d_in[2];
    const float* b1 = (const float*)d_in[3];
    const float* w2 = (const float*)d_in[4];
    const float* b2 = (const float*)d_in[5];
    const float* w3 = (const float*)d_in[6];
    const float* b3 = (const float*)d_in[7];
    const float* w4 = (const float*)d_in[8];
    const float* b4 = (const float*)d_in[9];
    float* out = (float*)d_out;

    static int attr_set = 0;
    if (!attr_set) {
        cudaFuncSetAttribute(monnn_kernel,
                             cudaFuncAttributeMaxDynamicSharedMemorySize, SMEM_TOTAL);
        attr_set = 1;
    }
    monnn_kernel<<<BATCH / TM, NTHR, SMEM_TOTAL>>>(x, h, w1, b1, w2, b2, w3, b3, w4, b4, out);
}

// round 6
// speedup vs baseline: 3.9863x; 1.3999x over previous
#include <cuda_runtime.h>
#include <cuda_bf16.h>
#include <math.h>
#include <stdint.h>

// MonotonicNN via mma.sync (HMMA) 2-term split-A bf16 GEMMs.
// Grid: 128 CTAs x 512 thr. CTA owns 128 batch rows, loops 51 quad points.
// Warp w: m-strip (w&7)*16, n-half (w>>3)*64 -> 8 m16n8 accum tiles.
// W2/W3 stored bf16 (rn) in XOR-swizzled 256B-row tiles; A split hi/lo.
// All smem tile accesses conflict-free (chunk-XOR swizzle), B+A via ldmatrix.

#define NTHR  512
#define TM    128
#define NS    51
#define NB    50
#define BATCH 16384
#define HID   128

// tile: 128 rows x 256 B; byte(r,k) = r*256 + 16*((k>>3)^(r&7)) + (k&7)*2
#define TILE_B   32768
#define OFF_W2   0
#define OFF_W3   (1 * TILE_B)
#define OFF_AHI  (2 * TILE_B)
#define OFF_ALO  (3 * TILE_B)
#define OFF_MISC (4 * TILE_B)          // 131072
// float-indexed misc: [0,256) W1 | [256,384) B1 | [384,512) B2 | [512,640) B3
// [640,768) W4 | [768,896) X | [896,1024) H | [1024,1088) CCW | [1088,1344) PART | [1344] b4
#define SMEM_TOTAL (OFF_MISC + 1360 * 4)

__device__ __forceinline__ void mma_bf16(float* c, const uint32_t* a,
                                         uint32_t b0, uint32_t b1) {
    asm volatile(
        "mma.sync.aligned.m16n8k16.row.col.f32.bf16.bf16.f32 "
        "{%0,%1,%2,%3}, {%4,%5,%6,%7}, {%8,%9}, {%0,%1,%2,%3};"
        : "+f"(c[0]), "+f"(c[1]), "+f"(c[2]), "+f"(c[3])
        : "r"(a[0]), "r"(a[1]), "r"(a[2]), "r"(a[3]), "r"(b0), "r"(b1));
}

#define LDSM_X4(r, addr) \
    asm volatile("ldmatrix.sync.aligned.m8n8.x4.shared.b16 {%0,%1,%2,%3}, [%4];" \
        : "=r"((r)[0]), "=r"((r)[1]), "=r"((r)[2]), "=r"((r)[3]) : "r"(addr))

__device__ __forceinline__ uint32_t smem_to_u32(const void* p) {
    uint32_t a;
    asm("{ .reg .u64 t; cvta.to.shared.u64 t, %1; cvt.u32.u64 %0, t; }" : "=r"(a) : "l"(p));
    return a;
}

// split fp32 pair (v0=even elem, v1=odd) -> packed bf16x2 hi and lo (v0 low half)
__device__ __forceinline__ void split_pack(float v0, float v1, uint32_t& hi, uint32_t& lo) {
    asm("cvt.rn.bf16x2.f32 %0, %1, %2;" : "=r"(hi) : "f"(v1), "f"(v0));
    float h0 = __uint_as_float(hi << 16);
    float h1 = __uint_as_float(hi & 0xFFFF0000u);
    float l0 = v0 - h0;
    float l1 = v1 - h1;
    asm("cvt.rn.bf16x2.f32 %0, %1, %2;" : "=r"(lo) : "f"(l1), "f"(l0));
}

__global__ void __launch_bounds__(NTHR, 1)
monnn_kernel(const float* __restrict__ x,  const float* __restrict__ h,
             const float* __restrict__ w1, const float* __restrict__ b1,
             const float* __restrict__ w2, const float* __restrict__ b2,
             const float* __restrict__ w3, const float* __restrict__ b3,
             const float* __restrict__ w4, const float* __restrict__ b4,
             float* __restrict__ out) {
    extern __shared__ char smem[];
    float* FM   = (float*)(smem + OFF_MISC);
    float* sW1  = FM;          float* sB1 = FM + 256;
    float* sB2  = FM + 384;    float* sB3 = FM + 512;
    float* sW4  = FM + 640;    float* sX  = FM + 768;
    float* sH   = FM + 896;    float* sCCW = FM + 1024;
    float* sPART = FM + 1088;  // [128][2]

    const int tid  = threadIdx.x;
    const int wid  = tid >> 5;
    const int lane = tid & 31;
    const int mbase = (wid & 7) * 16;     // warp m-strip
    const int nh    = wid >> 3;           // n-half 0/1
    const int nbase = nh * 64;
    const int bbase = blockIdx.x * TM;

    // ---- prologue: misc params ----
    for (int i = tid; i < 256; i += NTHR) sW1[i] = w1[i];
    if (tid < 128) {
        sB1[tid] = b1[tid]; sB2[tid] = b2[tid]; sB3[tid] = b3[tid];
        sW4[tid] = w4[tid];
        sX[tid] = x[bbase + tid]; sH[tid] = h[bbase + tid];
    }
    if (tid < NS) {  // Clenshaw-Curtis weights (fp32 cospif, validated)
        float acw = 0.0f;
        #pragma unroll 1
        for (int i = 0; i <= NB; i++) {
            float Wi = (i == 0) ? 1.0f : ((i & 1) ? 0.0f : 2.0f / (1.0f - (float)(i * i)));
            acw = fmaf(cospif((float)(i * tid) / (float)NB), Wi, acw);
        }
        acw *= 2.0f / (float)NB;
        if (tid == 0 || tid == NB) acw *= 0.5f;
        sCCW[tid] = acw;
    }
    if (tid == 0) FM[1344] = b4[0];

    // ---- prologue: W2,W3 -> transposed bf16 swizzled tiles Wt[j][k] (rn) ----
    // task: mtx | kp(0..63) | j(0..127); lanes cover consecutive j (coalesced LDG)
    for (int t = tid; t < 2 * 8192; t += NTHR) {
        int mtx = t >> 13;
        int r   = t & 8191;
        int kp  = r >> 7;           // k-pair index
        int j   = r & 127;
        int k   = kp * 2;
        const float* W = mtx ? w3 : w2;
        float v0 = W[k * 128 + j];
        float v1 = W[(k + 1) * 128 + j];
        uint32_t hp;
        asm("cvt.rn.bf16x2.f32 %0, %1, %2;" : "=r"(hp) : "f"(v1), "f"(v0));
        uint32_t off = (mtx ? OFF_W3 : OFF_W2)
                     + (uint32_t)j * 256u
                     + 16u * ((uint32_t)(k >> 3) ^ (uint32_t)(j & 7))
                     + (uint32_t)(kp & 3) * 4u;
        *(uint32_t*)(smem + off) = hp;
    }
    __syncthreads();

    // ---- per-thread constants ----
    const int r0 = mbase + (lane >> 2);        // c/a-frag row 0
    const int r1 = r0 + 8;                     // c/a-frag row 1
    const int kq = (lane & 3) * 2;             // frag col/k pair base
    const float xm0 = sX[r0], xm1 = sX[r1];
    const float hm0 = sH[r0], hm1 = sH[r1];
    const float b4v = FM[1344];
    const uint32_t sb = smem_to_u32(smem);
    const int lane7 = lane & 7;
    // B-ldmatrix lane constants: mi = lane>>3; matrix: tile 2g+(mi>>1), chunk 2ks+(mi&1)
    const uint32_t nB  = (uint32_t)(nbase + 8 * ((lane >> 3) >> 1) + lane7);
    const uint32_t n7B = nB & 7u;
    const uint32_t cB  = (uint32_t)((lane >> 3) & 1);
    const uint32_t rowB = nB * 256u;                 // + g*4096
    // A-ldmatrix lane constants: row rA, chunk 2ks + cA; rA&7 == lane7
    const uint32_t rA  = (uint32_t)(mbase + ((lane >> 3) & 1) * 8 + lane7);
    const uint32_t rowA = rA * 256u;
    const uint32_t cA  = (uint32_t)(lane >> 4);
    // epilogue store swizzle per tile t: 16*((8*nh+t)^(lane>>2)) + (lane&3)*4
    const uint32_t swS_base = (uint32_t)(lane >> 2);
    const uint32_t swS_q = (uint32_t)(lane & 3) * 4u;

    float zacc = 0.0f;

    for (int s = 0; s < NS; s++) {
        const float tS = (cospif((float)s / (float)NB) + 1.0f) * 0.5f;
        const float xs0 = xm0 * tS, xs1 = xm1 * tS;

        // ================= layer 2 (L1 fused, A frags built in registers) =================
        float acc[8][4];
        #pragma unroll
        for (int t = 0; t < 8; t++)
            #pragma unroll
            for (int q = 0; q < 4; q++) acc[t][q] = 0.0f;

        #pragma unroll 1
        for (int ks = 0; ks < 8; ks++) {
            uint32_t ahi[4], alo[4];
            #pragma unroll
            for (int j = 0; j < 2; j++) {
                int k = ks * 16 + kq + 8 * j;
                float2 wa = *(const float2*)&sW1[k];
                float2 wb = *(const float2*)&sW1[128 + k];
                float2 bb = *(const float2*)&sB1[k];
                float v00 = fmaxf(fmaf(xs0, wa.x, fmaf(hm0, wb.x, bb.x)), 0.0f);
                float v01 = fmaxf(fmaf(xs0, wa.y, fmaf(hm0, wb.y, bb.y)), 0.0f);
                float v10 = fmaxf(fmaf(xs1, wa.x, fmaf(hm1, wb.x, bb.x)), 0.0f);
                float v11 = fmaxf(fmaf(xs1, wa.y, fmaf(hm1, wb.y, bb.y)), 0.0f);
                split_pack(v00, v01, ahi[2 * j],     alo[2 * j]);
                split_pack(v10, v11, ahi[2 * j + 1], alo[2 * j + 1]);
            }
            const uint32_t swb = (((uint32_t)(2 * ks) + cB) ^ n7B) * 16u;
            #pragma unroll
            for (int g = 0; g < 4; g++) {
                uint32_t bq[4];
                LDSM_X4(bq, sb + OFF_W2 + rowB + (uint32_t)g * 4096u + swb);
                mma_bf16(acc[2 * g],     ahi, bq[0], bq[1]);
                mma_bf16(acc[2 * g],     alo, bq[0], bq[1]);
                mma_bf16(acc[2 * g + 1], ahi, bq[2], bq[3]);
                mma_bf16(acc[2 * g + 1], alo, bq[2], bq[3]);
            }
        }

        __syncthreads();   // prev-iter L3 A-reads + sPART combine done

        // ---- L2 epilogue: relu(D+b2) -> split-bf16 A tiles (swizzled stores) ----
        #pragma unroll
        for (int t = 0; t < 8; t++) {
            int n0 = nbase + 8 * t + kq;
            float2 b2v = *(const float2*)&sB2[n0];
            float v0 = fmaxf(acc[t][0] + b2v.x, 0.0f);
            float v1 = fmaxf(acc[t][1] + b2v.y, 0.0f);
            float v2 = fmaxf(acc[t][2] + b2v.x, 0.0f);
            float v3 = fmaxf(acc[t][3] + b2v.y, 0.0f);
            uint32_t sw = ((uint32_t)(8 * nh + t) ^ swS_base) * 16u + swS_q;
            uint32_t hi, lo;
            split_pack(v0, v1, hi, lo);
            *(uint32_t*)(smem + OFF_AHI + (uint32_t)r0 * 256u + sw) = hi;
            *(uint32_t*)(smem + OFF_ALO + (uint32_t)r0 * 256u + sw) = lo;
            split_pack(v2, v3, hi, lo);
            *(uint32_t*)(smem + OFF_AHI + (uint32_t)r1 * 256u + sw) = hi;
            *(uint32_t*)(smem + OFF_ALO + (uint32_t)r1 * 256u + sw) = lo;
        }
        __syncthreads();

        // ================= layer 3 (A via ldmatrix, swizzled) =================
        #pragma unroll
        for (int t = 0; t < 8; t++)
            #pragma unroll
            for (int q = 0; q < 4; q++) acc[t][q] = 0.0f;

        #pragma unroll 1
        for (int ks = 0; ks < 8; ks++) {
            uint32_t ahi[4], alo[4];
            const uint32_t swa = (((uint32_t)(2 * ks) + cA) ^ (uint32_t)lane7) * 16u;
            LDSM_X4(ahi, sb + OFF_AHI + rowA + swa);
            LDSM_X4(alo, sb + OFF_ALO + rowA + swa);
            const uint32_t swb = (((uint32_t)(2 * ks) + cB) ^ n7B) * 16u;
            #pragma unroll
            for (int g = 0; g < 4; g++) {
                uint32_t bq[4];
                LDSM_X4(bq, sb + OFF_W3 + rowB + (uint32_t)g * 4096u + swb);
                mma_bf16(acc[2 * g],     ahi, bq[0], bq[1]);
                mma_bf16(acc[2 * g],     alo, bq[0], bq[1]);
                mma_bf16(acc[2 * g + 1], ahi, bq[2], bq[3]);
                mma_bf16(acc[2 * g + 1], alo, bq[2], bq[3]);
            }
        }

        // ---- layer 4: dot(relu(D+b3), w4) ----
        float p0 = 0.0f, p1 = 0.0f;
        #pragma unroll
        for (int t = 0; t < 8; t++) {
            int n0 = nbase + 8 * t + kq;
            float2 b3v = *(const float2*)&sB3[n0];
            float2 w4v = *(const float2*)&sW4[n0];
            p0 = fmaf(fmaxf(acc[t][0] + b3v.x, 0.0f), w4v.x, p0);
            p0 = fmaf(fmaxf(acc[t][1] + b3v.y, 0.0f), w4v.y, p0);
            p1 = fmaf(fmaxf(acc[t][2] + b3v.x, 0.0f), w4v.x, p1);
            p1 = fmaf(fmaxf(acc[t][3] + b3v.y, 0.0f), w4v.y, p1);
        }
        p0 += __shfl_xor_sync(0xFFFFFFFFu, p0, 1);
        p0 += __shfl_xor_sync(0xFFFFFFFFu, p0, 2);
        p1 += __shfl_xor_sync(0xFFFFFFFFu, p1, 1);
        p1 += __shfl_xor_sync(0xFFFFFFFFu, p1, 2);
        if ((lane & 3) == 0) {
            sPART[r0 * 2 + nh] = p0;
            sPART[r1 * 2 + nh] = p1;
        }
        __syncthreads();

        if (tid < 128) {
            float v = sPART[tid * 2] + sPART[tid * 2 + 1] + b4v;
            float e = (v > 0.0f) ? v : expm1f(v);   // elu
            zacc = fmaf(sCCW[s], e + 1.0f, zacc);
        }
    }

    if (tid < 128)
        out[bbase + tid] = fmaf(zacc, 0.5f * sX[tid], sH[tid]);
}

extern "C" void kernel_launch(void* const* d_in, const int* in_sizes, int n_in,
                              void* d_out, int out_size) {
    const float* x  = (const float*)d_in[0];
    const float* h  = (const float*)d_in[1];
    const float* w1 = (const float*)d_in[2];
    const float* b1 = (const float*)d_in[3];
    const float* w2 = (const float*)d_in[4];
    const float* b2 = (const float*)d_in[5];
    const float* w3 = (const float*)d_in[6];
    const float* b3 = (const float*)d_in[7];
    const float* w4 = (const float*)d_in[8];
    const float* b4 = (const float*)d_in[9];
    float* out = (float*)d_out;

    static int attr_set = 0;
    if (!attr_set) {
        cudaFuncSetAttribute(monnn_kernel,
                             cudaFuncAttributeMaxDynamicSharedMemorySize, SMEM_TOTAL);
        attr_set = 1;
    }
    monnn_kernel<<<BATCH / TM, NTHR, SMEM_TOTAL>>>(x, h, w1, b1, w2, b2, w3, b3, w4, b4, out);
}

// round 7
// speedup vs baseline: 6.8825x; 1.7265x over previous
#include <cuda_runtime.h>
#include <cuda_bf16.h>
#include <math.h>
#include <stdint.h>

// MonotonicNN via HMMA bf16, register-resident layer chaining.
// Grid: 128 CTAs x 256 thr (8 warps). Warp owns m16 strip x all 128 n.
// L2 C-frags are converted in-register to L3 A-frags (identical layouts);
// no smem activation tiles, no syncthreads in the s-loop.
// W2/W3 bf16 in XOR-swizzled 256B-row tiles (validated R6), B via ldmatrix.

#define NTHR  256
#define TM    128
#define NS    51
#define NB    50
#define BATCH 16384
#define HID   128

// tile: 128 rows x 256 B; byte(r,k) = r*256 + 16*((k>>3)^(r&7)) + (k&7)*2
#define TILE_B   32768
#define OFF_W2   0
#define OFF_W3   TILE_B
#define OFF_MISC (2 * TILE_B)   // 65536
// float-indexed misc: [0,256) W1 | [256,384) B1 | [384,512) B2 | [512,640) B3
// [640,768) W4 | [768,896) X | [896,1024) H | [1024,1088) CCW | [1088] b4
#define SMEM_TOTAL (OFF_MISC + 1104 * 4)

__device__ __forceinline__ void mma_bf16(float* c, const uint32_t* a,
                                         uint32_t b0, uint32_t b1) {
    asm volatile(
        "mma.sync.aligned.m16n8k16.row.col.f32.bf16.bf16.f32 "
        "{%0,%1,%2,%3}, {%4,%5,%6,%7}, {%8,%9}, {%0,%1,%2,%3};"
        : "+f"(c[0]), "+f"(c[1]), "+f"(c[2]), "+f"(c[3])
        : "r"(a[0]), "r"(a[1]), "r"(a[2]), "r"(a[3]), "r"(b0), "r"(b1));
}

#define LDSM_X4(r, addr) \
    asm volatile("ldmatrix.sync.aligned.m8n8.x4.shared.b16 {%0,%1,%2,%3}, [%4];" \
        : "=r"((r)[0]), "=r"((r)[1]), "=r"((r)[2]), "=r"((r)[3]) : "r"(addr))

__device__ __forceinline__ uint32_t smem_to_u32(const void* p) {
    uint32_t a;
    asm("{ .reg .u64 t; cvta.to.shared.u64 t, %1; cvt.u32.u64 %0, t; }" : "=r"(a) : "l"(p));
    return a;
}

// pack two fp32 -> bf16x2 (v0 in low half)
__device__ __forceinline__ uint32_t pack_bf16(float v0, float v1) {
    uint32_t r;
    asm("cvt.rn.bf16x2.f32 %0, %1, %2;" : "=r"(r) : "f"(v1), "f"(v0));
    return r;
}

__global__ void __launch_bounds__(NTHR, 1)
monnn_kernel(const float* __restrict__ x,  const float* __restrict__ h,
             const float* __restrict__ w1, const float* __restrict__ b1,
             const float* __restrict__ w2, const float* __restrict__ b2,
             const float* __restrict__ w3, const float* __restrict__ b3,
             const float* __restrict__ w4, const float* __restrict__ b4,
             float* __restrict__ out) {
    extern __shared__ char smem[];
    float* FM  = (float*)(smem + OFF_MISC);
    float* sW1 = FM;          float* sB1 = FM + 256;
    float* sB2 = FM + 384;    float* sB3 = FM + 512;
    float* sW4 = FM + 640;    float* sX  = FM + 768;
    float* sH  = FM + 896;    float* sCCW = FM + 1024;

    const int tid  = threadIdx.x;
    const int wid  = tid >> 5;
    const int lane = tid & 31;
    const int mbase = wid * 16;           // warp m-strip (8 warps x 16 rows)
    const int bbase = blockIdx.x * TM;

    // ---- prologue: misc params ----
    if (tid < 256) sW1[tid] = w1[tid];
    if (tid < 128) {
        sB1[tid] = b1[tid]; sB2[tid] = b2[tid]; sB3[tid] = b3[tid];
        sW4[tid] = w4[tid];
        sX[tid] = x[bbase + tid]; sH[tid] = h[bbase + tid];
    }
    if (tid < NS) {  // Clenshaw-Curtis weights (fp32 cospif, validated)
        float acw = 0.0f;
        #pragma unroll 1
        for (int i = 0; i <= NB; i++) {
            float Wi = (i == 0) ? 1.0f : ((i & 1) ? 0.0f : 2.0f / (1.0f - (float)(i * i)));
            acw = fmaf(cospif((float)(i * tid) / (float)NB), Wi, acw);
        }
        acw *= 2.0f / (float)NB;
        if (tid == 0 || tid == NB) acw *= 0.5f;
        sCCW[tid] = acw;
    }
    if (tid == 0) FM[1088] = b4[0];

    // ---- prologue: W2,W3 -> transposed bf16 swizzled tiles Wt[j][k] ----
    for (int t = tid; t < 2 * 8192; t += NTHR) {
        int mtx = t >> 13;
        int r   = t & 8191;
        int kp  = r >> 7;           // k-pair index
        int j   = r & 127;
        int k   = kp * 2;
        const float* W = mtx ? w3 : w2;
        float v0 = W[k * 128 + j];
        float v1 = W[(k + 1) * 128 + j];
        uint32_t hp = pack_bf16(v0, v1);
        uint32_t off = (mtx ? OFF_W3 : OFF_W2)
                     + (uint32_t)j * 256u
                     + 16u * ((uint32_t)(k >> 3) ^ (uint32_t)(j & 7))
                     + (uint32_t)(kp & 3) * 4u;
        *(uint32_t*)(smem + off) = hp;
    }
    __syncthreads();

    // ---- per-thread constants ----
    const int r0 = mbase + (lane >> 2);        // frag row 0
    const int r1 = r0 + 8;                     // frag row 1
    const int kq = (lane & 3) * 2;             // frag col/k pair base
    const float xm0 = sX[r0], xm1 = sX[r1];
    const float hm0 = sH[r0], hm1 = sH[r1];
    const float b4v = FM[1088];
    const uint32_t sb = smem_to_u32(smem);
    const int lane7 = lane & 7;
    // B-ldmatrix lane constants (validated R6): mi = lane>>3
    // matrix mi -> n-tile 2g+(mi>>1), k-chunk 2ks+(mi&1)
    const uint32_t nB  = (uint32_t)(8 * ((lane >> 3) >> 1) + lane7);
    const uint32_t n7B = nB & 7u;
    const uint32_t cB  = (uint32_t)((lane >> 3) & 1);
    const uint32_t rowB = nB * 256u;           // + g*4096

    float z0 = 0.0f, z1 = 0.0f;

    for (int s = 0; s < NS; s++) {
        const float tS = (cospif((float)s / (float)NB) + 1.0f) * 0.5f;
        const float xs0 = xm0 * tS, xs1 = xm1 * tS;

        float acc[16][4];
        #pragma unroll
        for (int t = 0; t < 16; t++)
            #pragma unroll
            for (int q = 0; q < 4; q++) acc[t][q] = 0.0f;

        // ============ layer 2 (L1 fused; A frag built in registers) ============
        #pragma unroll 1
        for (int ks = 0; ks < 8; ks++) {
            uint32_t a[4];
            #pragma unroll
            for (int j = 0; j < 2; j++) {
                int k = ks * 16 + kq + 8 * j;
                float2 wa = *(const float2*)&sW1[k];
                float2 wb = *(const float2*)&sW1[128 + k];
                float2 bb = *(const float2*)&sB1[k];
                float v00 = fmaxf(fmaf(xs0, wa.x, fmaf(hm0, wb.x, bb.x)), 0.0f);
                float v01 = fmaxf(fmaf(xs0, wa.y, fmaf(hm0, wb.y, bb.y)), 0.0f);
                float v10 = fmaxf(fmaf(xs1, wa.x, fmaf(hm1, wb.x, bb.x)), 0.0f);
                float v11 = fmaxf(fmaf(xs1, wa.y, fmaf(hm1, wb.y, bb.y)), 0.0f);
                a[2 * j]     = pack_bf16(v00, v01);
                a[2 * j + 1] = pack_bf16(v10, v11);
            }
            const uint32_t swb = (((uint32_t)(2 * ks) + cB) ^ n7B) * 16u;
            #pragma unroll
            for (int g = 0; g < 8; g++) {
                uint32_t bq[4];
                LDSM_X4(bq, sb + OFF_W2 + rowB + (uint32_t)g * 4096u + swb);
                mma_bf16(acc[2 * g],     a, bq[0], bq[1]);
                mma_bf16(acc[2 * g + 1], a, bq[2], bq[3]);
            }
        }

        // ---- in-register epilogue: relu(D+b2) -> L3 A-frags ----
        // tile t covers cols n=8t+kq,+1; af[2t]={r0}, af[2t+1]={r1}
        // for k-chunk ks, A-frag = {af[4ks], af[4ks+1], af[4ks+2], af[4ks+3]}
        uint32_t af[32];
        #pragma unroll
        for (int t = 0; t < 16; t++) {
            int n0 = 8 * t + kq;
            float2 b2v = *(const float2*)&sB2[n0];
            af[2 * t]     = pack_bf16(fmaxf(acc[t][0] + b2v.x, 0.0f),
                                      fmaxf(acc[t][1] + b2v.y, 0.0f));
            af[2 * t + 1] = pack_bf16(fmaxf(acc[t][2] + b2v.x, 0.0f),
                                      fmaxf(acc[t][3] + b2v.y, 0.0f));
        }

        #pragma unroll
        for (int t = 0; t < 16; t++)
            #pragma unroll
            for (int q = 0; q < 4; q++) acc[t][q] = 0.0f;

        // ============ layer 3 (A from registers, B via ldmatrix) ============
        #pragma unroll 1
        for (int ks = 0; ks < 8; ks++) {
            const uint32_t swb = (((uint32_t)(2 * ks) + cB) ^ n7B) * 16u;
            #pragma unroll
            for (int g = 0; g < 8; g++) {
                uint32_t bq[4];
                LDSM_X4(bq, sb + OFF_W3 + rowB + (uint32_t)g * 4096u + swb);
                mma_bf16(acc[2 * g],     &af[4 * ks], bq[0], bq[1]);
                mma_bf16(acc[2 * g + 1], &af[4 * ks], bq[2], bq[3]);
            }
        }

        // ---- layer 4: dot(relu(D+b3), w4), quad shfl-reduce (same row) ----
        float p0 = 0.0f, p1 = 0.0f;
        #pragma unroll
        for (int t = 0; t < 16; t++) {
            int n0 = 8 * t + kq;
            float2 b3v = *(const float2*)&sB3[n0];
            float2 w4v = *(const float2*)&sW4[n0];
            p0 = fmaf(fmaxf(acc[t][0] + b3v.x, 0.0f), w4v.x, p0);
            p0 = fmaf(fmaxf(acc[t][1] + b3v.y, 0.0f), w4v.y, p0);
            p1 = fmaf(fmaxf(acc[t][2] + b3v.x, 0.0f), w4v.x, p1);
            p1 = fmaf(fmaxf(acc[t][3] + b3v.y, 0.0f), w4v.y, p1);
        }
        p0 += __shfl_xor_sync(0xFFFFFFFFu, p0, 1);
        p0 += __shfl_xor_sync(0xFFFFFFFFu, p0, 2);
        p1 += __shfl_xor_sync(0xFFFFFFFFu, p1, 1);
        p1 += __shfl_xor_sync(0xFFFFFFFFu, p1, 2);

        float ccw = sCCW[s];
        float v0 = p0 + b4v;
        float v1 = p1 + b4v;
        float e0 = (v0 > 0.0f) ? v0 : expm1f(v0);   // elu
        float e1 = (v1 > 0.0f) ? v1 : expm1f(v1);
        z0 = fmaf(ccw, e0 + 1.0f, z0);
        z1 = fmaf(ccw, e1 + 1.0f, z1);
    }

    if ((lane & 3) == 0) {
        out[bbase + r0] = fmaf(z0, 0.5f * xm0, hm0);
        out[bbase + r1] = fmaf(z1, 0.5f * xm1, hm1);
    }
}

extern "C" void kernel_launch(void* const* d_in, const int* in_sizes, int n_in,
                              void* d_out, int out_size) {
    const float* x  = (const float*)d_in[0];
    const float* h  = (const float*)d_in[1];
    const float* w1 = (const float*)d_in[2];
    const float* b1 = (const float*)d_in[3];
    const float* w2 = (const float*)d_in[4];
    const float* b2 = (const float*)d_in[5];
    const float* w3 = (const float*)d_in[6];
    const float* b3 = (const float*)d_in[7];
    const float* w4 = (const float*)d_in[8];
    const float* b4 = (const float*)d_in[9];
    float* out = (float*)d_out;

    static int attr_set = 0;
    if (!attr_set) {
        cudaFuncSetAttribute(monnn_kernel,
                             cudaFuncAttributeMaxDynamicSharedMemorySize, SMEM_TOTAL);
        attr_set = 1;
    }
    monnn_kernel<<<BATCH / TM, NTHR, SMEM_TOTAL>>>(x, h, w1, b1, w2, b2, w3, b3, w4, b4, out);
}

// round 8
// speedup vs baseline: 7.2411x; 1.0521x over previous
#include <cuda_runtime.h>
#include <cuda_bf16.h>
#include <math.h>
#include <stdint.h>

// MonotonicNN via HMMA bf16, register-resident layer chaining + s-split.
// Grid: 128 CTAs x 512 thr (16 warps). Warp w: m-strip (w&7)*16, quad subset
// s in {w>>3, +2, ...}. All layers chained in registers per (s, m-strip);
// no smem activation tiles; one final cross-group combine.
// W2/W3 bf16 in XOR-swizzled 256B-row tiles, B via ldmatrix (validated R6/R7).

#define NTHR  512
#define TM    128
#define NS    51
#define NB    50
#define BATCH 16384
#define HID   128

// tile: 128 rows x 256 B; byte(r,k) = r*256 + 16*((k>>3)^(r&7)) + (k&7)*2
#define TILE_B   32768
#define OFF_W2   0
#define OFF_W3   TILE_B
#define OFF_MISC (2 * TILE_B)   // 65536
// float-indexed misc: [0,256) W1 | [256,384) B1 | [384,512) B2 | [512,640) B3
// [640,768) W4 | [768,896) X | [896,1024) H | [1024,1088) CCW | [1088] b4 |
// [1092,1348) ZP (2x128 partials)
#define SMEM_TOTAL (OFF_MISC + 1360 * 4)

__device__ __forceinline__ void mma_bf16(float* c, const uint32_t* a,
                                         uint32_t b0, uint32_t b1) {
    asm volatile(
        "mma.sync.aligned.m16n8k16.row.col.f32.bf16.bf16.f32 "
        "{%0,%1,%2,%3}, {%4,%5,%6,%7}, {%8,%9}, {%0,%1,%2,%3};"
        : "+f"(c[0]), "+f"(c[1]), "+f"(c[2]), "+f"(c[3])
        : "r"(a[0]), "r"(a[1]), "r"(a[2]), "r"(a[3]), "r"(b0), "r"(b1));
}

#define LDSM_X4(r, addr) \
    asm volatile("ldmatrix.sync.aligned.m8n8.x4.shared.b16 {%0,%1,%2,%3}, [%4];" \
        : "=r"((r)[0]), "=r"((r)[1]), "=r"((r)[2]), "=r"((r)[3]) : "r"(addr))

__device__ __forceinline__ uint32_t smem_to_u32(const void* p) {
    uint32_t a;
    asm("{ .reg .u64 t; cvta.to.shared.u64 t, %1; cvt.u32.u64 %0, t; }" : "=r"(a) : "l"(p));
    return a;
}

// pack two fp32 -> bf16x2 (v0 in low half)
__device__ __forceinline__ uint32_t pack_bf16(float v0, float v1) {
    uint32_t r;
    asm("cvt.rn.bf16x2.f32 %0, %1, %2;" : "=r"(r) : "f"(v1), "f"(v0));
    return r;
}

__global__ void __launch_bounds__(NTHR, 1)
monnn_kernel(const float* __restrict__ x,  const float* __restrict__ h,
             const float* __restrict__ w1, const float* __restrict__ b1,
             const float* __restrict__ w2, const float* __restrict__ b2,
             const float* __restrict__ w3, const float* __restrict__ b3,
             const float* __restrict__ w4, const float* __restrict__ b4,
             float* __restrict__ out) {
    extern __shared__ char smem[];
    float* FM  = (float*)(smem + OFF_MISC);
    float* sW1 = FM;          float* sB1 = FM + 256;
    float* sB2 = FM + 384;    float* sB3 = FM + 512;
    float* sW4 = FM + 640;    float* sX  = FM + 768;
    float* sH  = FM + 896;    float* sCCW = FM + 1024;
    float* sZP = FM + 1092;   // [2][128] partials

    const int tid  = threadIdx.x;
    const int wid  = tid >> 5;
    const int lane = tid & 31;
    const int mbase = (wid & 7) * 16;     // warp m-strip
    const int sg    = wid >> 3;           // s-group 0/1
    const int bbase = blockIdx.x * TM;

    // ---- prologue: misc params ----
    if (tid < 256) sW1[tid] = w1[tid];
    if (tid < 128) {
        sB1[tid] = b1[tid]; sB2[tid] = b2[tid]; sB3[tid] = b3[tid];
        sW4[tid] = w4[tid];
        sX[tid] = x[bbase + tid]; sH[tid] = h[bbase + tid];
    }
    if (tid < NS) {  // Clenshaw-Curtis weights (fp32 cospif, validated)
        float acw = 0.0f;
        #pragma unroll 1
        for (int i = 0; i <= NB; i++) {
            float Wi = (i == 0) ? 1.0f : ((i & 1) ? 0.0f : 2.0f / (1.0f - (float)(i * i)));
            acw = fmaf(cospif((float)(i * tid) / (float)NB), Wi, acw);
        }
        acw *= 2.0f / (float)NB;
        if (tid == 0 || tid == NB) acw *= 0.5f;
        sCCW[tid] = acw;
    }
    if (tid == 0) FM[1088] = b4[0];

    // ---- prologue: W2,W3 -> transposed bf16 swizzled tiles Wt[j][k] ----
    for (int t = tid; t < 2 * 8192; t += NTHR) {
        int mtx = t >> 13;
        int r   = t & 8191;
        int kp  = r >> 7;           // k-pair index
        int j   = r & 127;
        int k   = kp * 2;
        const float* W = mtx ? w3 : w2;
        float v0 = W[k * 128 + j];
        float v1 = W[(k + 1) * 128 + j];
        uint32_t hp = pack_bf16(v0, v1);
        uint32_t off = (mtx ? OFF_W3 : OFF_W2)
                     + (uint32_t)j * 256u
                     + 16u * ((uint32_t)(k >> 3) ^ (uint32_t)(j & 7))
                     + (uint32_t)(kp & 3) * 4u;
        *(uint32_t*)(smem + off) = hp;
    }
    __syncthreads();

    // ---- per-thread constants ----
    const int r0 = mbase + (lane >> 2);        // frag row 0
    const int r1 = r0 + 8;                     // frag row 1
    const int kq = (lane & 3) * 2;             // frag col/k pair base
    const float xm0 = sX[r0], xm1 = sX[r1];
    const float hm0 = sH[r0], hm1 = sH[r1];
    const float b4v = FM[1088];
    const uint32_t sb = smem_to_u32(smem);
    const int lane7 = lane & 7;
    // B-ldmatrix lane constants (validated): mi = lane>>3
    // matrix mi -> n-tile 2g+(mi>>1), k-chunk 2ks+(mi&1)
    const uint32_t nB  = (uint32_t)(8 * ((lane >> 3) >> 1) + lane7);
    const uint32_t n7B = nB & 7u;
    const uint32_t cB  = (uint32_t)((lane >> 3) & 1);
    const uint32_t rowB = nB * 256u;           // + g*4096

    float z0 = 0.0f, z1 = 0.0f;

    for (int s = sg; s < NS; s += 2) {
        const float tS = (cospif((float)s / (float)NB) + 1.0f) * 0.5f;
        const float xs0 = xm0 * tS, xs1 = xm1 * tS;

        float acc[16][4];
        #pragma unroll
        for (int t = 0; t < 16; t++)
            #pragma unroll
            for (int q = 0; q < 4; q++) acc[t][q] = 0.0f;

        // ============ layer 2 (L1 fused; A frag built in registers) ============
        #pragma unroll 1
        for (int ks = 0; ks < 8; ks++) {
            uint32_t a[4];
            #pragma unroll
            for (int j = 0; j < 2; j++) {
                int k = ks * 16 + kq + 8 * j;
                float2 wa = *(const float2*)&sW1[k];
                float2 wb = *(const float2*)&sW1[128 + k];
                float2 bb = *(const float2*)&sB1[k];
                float v00 = fmaxf(fmaf(xs0, wa.x, fmaf(hm0, wb.x, bb.x)), 0.0f);
                float v01 = fmaxf(fmaf(xs0, wa.y, fmaf(hm0, wb.y, bb.y)), 0.0f);
                float v10 = fmaxf(fmaf(xs1, wa.x, fmaf(hm1, wb.x, bb.x)), 0.0f);
                float v11 = fmaxf(fmaf(xs1, wa.y, fmaf(hm1, wb.y, bb.y)), 0.0f);
                a[2 * j]     = pack_bf16(v00, v01);
                a[2 * j + 1] = pack_bf16(v10, v11);
            }
            const uint32_t swb = (((uint32_t)(2 * ks) + cB) ^ n7B) * 16u;
            #pragma unroll
            for (int g = 0; g < 8; g++) {
                uint32_t bq[4];
                LDSM_X4(bq, sb + OFF_W2 + rowB + (uint32_t)g * 4096u + swb);
                mma_bf16(acc[2 * g],     a, bq[0], bq[1]);
                mma_bf16(acc[2 * g + 1], a, bq[2], bq[3]);
            }
        }

        // ---- in-register epilogue: relu(D+b2) -> L3 A-frags ----
        uint32_t af[32];
        #pragma unroll
        for (int t = 0; t < 16; t++) {
            int n0 = 8 * t + kq;
            float2 b2v = *(const float2*)&sB2[n0];
            af[2 * t]     = pack_bf16(fmaxf(acc[t][0] + b2v.x, 0.0f),
                                      fmaxf(acc[t][1] + b2v.y, 0.0f));
            af[2 * t + 1] = pack_bf16(fmaxf(acc[t][2] + b2v.x, 0.0f),
                                      fmaxf(acc[t][3] + b2v.y, 0.0f));
        }

        #pragma unroll
        for (int t = 0; t < 16; t++)
            #pragma unroll
            for (int q = 0; q < 4; q++) acc[t][q] = 0.0f;

        // ============ layer 3 (A from registers, B via ldmatrix) ============
        #pragma unroll 1
        for (int ks = 0; ks < 8; ks++) {
            const uint32_t swb = (((uint32_t)(2 * ks) + cB) ^ n7B) * 16u;
            #pragma unroll
            for (int g = 0; g < 8; g++) {
                uint32_t bq[4];
                LDSM_X4(bq, sb + OFF_W3 + rowB + (uint32_t)g * 4096u + swb);
                mma_bf16(acc[2 * g],     &af[4 * ks], bq[0], bq[1]);
                mma_bf16(acc[2 * g + 1], &af[4 * ks], bq[2], bq[3]);
            }
        }

        // ---- layer 4: dot(relu(D+b3), w4), quad shfl-reduce (same row) ----
        float p0 = 0.0f, p1 = 0.0f;
        #pragma unroll
        for (int t = 0; t < 16; t++) {
            int n0 = 8 * t + kq;
            float2 b3v = *(const float2*)&sB3[n0];
            float2 w4v = *(const float2*)&sW4[n0];
            p0 = fmaf(fmaxf(acc[t][0] + b3v.x, 0.0f), w4v.x, p0);
            p0 = fmaf(fmaxf(acc[t][1] + b3v.y, 0.0f), w4v.y, p0);
            p1 = fmaf(fmaxf(acc[t][2] + b3v.x, 0.0f), w4v.x, p1);
            p1 = fmaf(fmaxf(acc[t][3] + b3v.y, 0.0f), w4v.y, p1);
        }
        p0 += __shfl_xor_sync(0xFFFFFFFFu, p0, 1);
        p0 += __shfl_xor_sync(0xFFFFFFFFu, p0, 2);
        p1 += __shfl_xor_sync(0xFFFFFFFFu, p1, 1);
        p1 += __shfl_xor_sync(0xFFFFFFFFu, p1, 2);

        float ccw = sCCW[s];
        float v0 = p0 + b4v;
        float v1 = p1 + b4v;
        float e0 = (v0 > 0.0f) ? v0 : expm1f(v0);   // elu
        float e1 = (v1 > 0.0f) ? v1 : expm1f(v1);
        z0 = fmaf(ccw, e0 + 1.0f, z0);
        z1 = fmaf(ccw, e1 + 1.0f, z1);
    }

    // ---- combine the two s-groups ----
    if ((lane & 3) == 0) {
        sZP[sg * 128 + r0] = z0;
        sZP[sg * 128 + r1] = z1;
    }
    __syncthreads();
    if (tid < 128) {
        float z = sZP[tid] + sZP[128 + tid];
        out[bbase + tid] = fmaf(z, 0.5f * sX[tid], sH[tid]);
    }
}

extern "C" void kernel_launch(void* const* d_in, const int* in_sizes, int n_in,
                              void* d_out, int out_size) {
    const float* x  = (const float*)d_in[0];
    const float* h  = (const float*)d_in[1];
    const float* w1 = (const float*)d_in[2];
    const float* b1 = (const float*)d_in[3];
    const float* w2 = (const float*)d_in[4];
    const float* b2 = (const float*)d_in[5];
    const float* w3 = (const float*)d_in[6];
    const float* b3 = (const float*)d_in[7];
    const float* w4 = (const float*)d_in[8];
    const float* b4 = (const float*)d_in[9];
    float* out = (float*)d_out;

    static int attr_set = 0;
    if (!attr_set) {
        cudaFuncSetAttribute(monnn_kernel,
                             cudaFuncAttributeMaxDynamicSharedMemorySize, SMEM_TOTAL);
        attr_set = 1;
    }
    monnn_kernel<<<BATCH / TM, NTHR, SMEM_TOTAL>>>(x, h, w1, b1, w2, b2, w3, b3, w4, b4, out);
}

// round 9
// speedup vs baseline: 8.3491x; 1.1530x over previous
#include <cuda_runtime.h>
#include <cuda_bf16.h>
#include <math.h>
#include <stdint.h>

// MonotonicNN via HMMA bf16, register-chained layers + s-PAIRING:
// each warp runs two quadrature chains (s0,s1) at once so every W2/W3
// ldmatrix feeds 4 MMAs (2 n-tiles x 2 s). GEMMs restructured g-outer/
// ks-inner in blocks of 4 n-tiles to keep only 32 accumulator regs live.
// Grid: 128 CTAs x 256 thr (8 warps, warp = m16 strip x n-full).
// W2/W3 bf16 in XOR-swizzled 256B-row tiles (validated R6-R8).

#define NTHR  256
#define TM    128
#define NS    51
#define NB    50
#define BATCH 16384
#define HID   128

// tile: 128 rows x 256 B; byte(r,k) = r*256 + 16*((k>>3)^(r&7)) + (k&7)*2
#define TILE_B   32768
#define OFF_W2   0
#define OFF_W3   TILE_B
#define OFF_MISC (2 * TILE_B)   // 65536
// float-indexed misc: [0,256) W1 | [256,384) B1 | [384,512) B2 | [512,640) B3
// [640,768) W4 | [768,896) X | [896,1024) H | [1024,1076) CCW(52) | [1076] b4
#define SMEM_TOTAL (OFF_MISC + 1088 * 4)

__device__ __forceinline__ void mma_bf16(float* c, const uint32_t* a,
                                         uint32_t b0, uint32_t b1) {
    asm volatile(
        "mma.sync.aligned.m16n8k16.row.col.f32.bf16.bf16.f32 "
        "{%0,%1,%2,%3}, {%4,%5,%6,%7}, {%8,%9}, {%0,%1,%2,%3};"
        : "+f"(c[0]), "+f"(c[1]), "+f"(c[2]), "+f"(c[3])
        : "r"(a[0]), "r"(a[1]), "r"(a[2]), "r"(a[3]), "r"(b0), "r"(b1));
}

#define LDSM_X4(r, addr) \
    asm volatile("ldmatrix.sync.aligned.m8n8.x4.shared.b16 {%0,%1,%2,%3}, [%4];" \
        : "=r"((r)[0]), "=r"((r)[1]), "=r"((r)[2]), "=r"((r)[3]) : "r"(addr))

__device__ __forceinline__ uint32_t smem_to_u32(const void* p) {
    uint32_t a;
    asm("{ .reg .u64 t; cvta.to.shared.u64 t, %1; cvt.u32.u64 %0, t; }" : "=r"(a) : "l"(p));
    return a;
}

// pack two fp32 -> bf16x2 (v0 in low half)
__device__ __forceinline__ uint32_t pack_bf16(float v0, float v1) {
    uint32_t r;
    asm("cvt.rn.bf16x2.f32 %0, %1, %2;" : "=r"(r) : "f"(v1), "f"(v0));
    return r;
}

__global__ void __launch_bounds__(NTHR, 1)
monnn_kernel(const float* __restrict__ x,  const float* __restrict__ h,
             const float* __restrict__ w1, const float* __restrict__ b1,
             const float* __restrict__ w2, const float* __restrict__ b2,
             const float* __restrict__ w3, const float* __restrict__ b3,
             const float* __restrict__ w4, const float* __restrict__ b4,
             float* __restrict__ out) {
    extern __shared__ char smem[];
    float* FM  = (float*)(smem + OFF_MISC);
    float* sW1 = FM;          float* sB1 = FM + 256;
    float* sB2 = FM + 384;    float* sB3 = FM + 512;
    float* sW4 = FM + 640;    float* sX  = FM + 768;
    float* sH  = FM + 896;    float* sCCW = FM + 1024;  // 52 entries

    const int tid  = threadIdx.x;
    const int wid  = tid >> 5;
    const int lane = tid & 31;
    const int mbase = wid * 16;           // warp m-strip (8 warps x 16 rows)
    const int bbase = blockIdx.x * TM;

    // ---- prologue: misc params ----
    sW1[tid] = w1[tid];                    // 256 threads, 256 elems
    if (tid < 128) {
        sB1[tid] = b1[tid]; sB2[tid] = b2[tid]; sB3[tid] = b3[tid];
        sW4[tid] = w4[tid];
        sX[tid] = x[bbase + tid]; sH[tid] = h[bbase + tid];
    }
    if (tid < 52) {  // Clenshaw-Curtis weights; [51] = 0 pads the odd pair
        float acw = 0.0f;
        if (tid <= NB) {
            #pragma unroll 1
            for (int i = 0; i <= NB; i++) {
                float Wi = (i == 0) ? 1.0f : ((i & 1) ? 0.0f : 2.0f / (1.0f - (float)(i * i)));
                acw = fmaf(cospif((float)(i * tid) / (float)NB), Wi, acw);
            }
            acw *= 2.0f / (float)NB;
            if (tid == 0 || tid == NB) acw *= 0.5f;
        }
        sCCW[tid] = acw;
    }
    if (tid == 0) FM[1076] = b4[0];

    // ---- prologue: W2,W3 -> transposed bf16 swizzled tiles Wt[j][k] ----
    for (int t = tid; t < 2 * 8192; t += NTHR) {
        int mtx = t >> 13;
        int r   = t & 8191;
        int kp  = r >> 7;           // k-pair index
        int j   = r & 127;
        int k   = kp * 2;
        const float* W = mtx ? w3 : w2;
        float v0 = W[k * 128 + j];
        float v1 = W[(k + 1) * 128 + j];
        uint32_t hp = pack_bf16(v0, v1);
        uint32_t off = (mtx ? OFF_W3 : OFF_W2)
                     + (uint32_t)j * 256u
                     + 16u * ((uint32_t)(k >> 3) ^ (uint32_t)(j & 7))
                     + (uint32_t)(kp & 3) * 4u;
        *(uint32_t*)(smem + off) = hp;
    }
    __syncthreads();

    // ---- per-thread constants ----
    const int r0 = mbase + (lane >> 2);        // frag row 0
    const int r1 = r0 + 8;                     // frag row 1
    const int kq = (lane & 3) * 2;             // frag col/k pair base
    const float xm0 = sX[r0], xm1 = sX[r1];
    const float hm0 = sH[r0], hm1 = sH[r1];
    const float b4v = FM[1076];
    const uint32_t sb = smem_to_u32(smem);
    const int lane7 = lane & 7;
    // B-ldmatrix lane constants (validated): mi = lane>>3
    // matrix mi -> n-tile 2g+(mi>>1), k-chunk 2ks+(mi&1)
    const uint32_t nB  = (uint32_t)(8 * ((lane >> 3) >> 1) + lane7);
    const uint32_t n7B = nB & 7u;
    const uint32_t cB  = (uint32_t)((lane >> 3) & 1);
    const uint32_t rowB = nB * 256u;           // + g*4096

    float z0 = 0.0f, z1 = 0.0f;

    #pragma unroll 1
    for (int sp = 0; sp < 26; sp++) {
        const int s0 = 2 * sp, s1 = 2 * sp + 1;
        const float tS0 = (cospif((float)s0 / (float)NB) + 1.0f) * 0.5f;
        const float tS1 = (cospif((float)s1 / (float)NB) + 1.0f) * 0.5f;
        const float xs00 = xm0 * tS0, xs01 = xm1 * tS0;
        const float xs10 = xm0 * tS1, xs11 = xm1 * tS1;

        // ---- layer 1 for both s: A-frags in registers (shared W1 loads) ----
        uint32_t aIn0[32], aIn1[32];
        #pragma unroll
        for (int ks = 0; ks < 8; ks++) {
            #pragma unroll
            for (int j = 0; j < 2; j++) {
                int k = ks * 16 + kq + 8 * j;
                float2 wa = *(const float2*)&sW1[k];
                float2 wb = *(const float2*)&sW1[128 + k];
                float2 bb = *(const float2*)&sB1[k];
                float c0x = fmaf(hm0, wb.x, bb.x), c0y = fmaf(hm0, wb.y, bb.y);
                float c1x = fmaf(hm1, wb.x, bb.x), c1y = fmaf(hm1, wb.y, bb.y);
                aIn0[4*ks + 2*j]     = pack_bf16(fmaxf(fmaf(xs00, wa.x, c0x), 0.0f),
                                                 fmaxf(fmaf(xs00, wa.y, c0y), 0.0f));
                aIn0[4*ks + 2*j + 1] = pack_bf16(fmaxf(fmaf(xs01, wa.x, c1x), 0.0f),
                                                 fmaxf(fmaf(xs01, wa.y, c1y), 0.0f));
                aIn1[4*ks + 2*j]     = pack_bf16(fmaxf(fmaf(xs10, wa.x, c0x), 0.0f),
                                                 fmaxf(fmaf(xs10, wa.y, c0y), 0.0f));
                aIn1[4*ks + 2*j + 1] = pack_bf16(fmaxf(fmaf(xs11, wa.x, c1x), 0.0f),
                                                 fmaxf(fmaf(xs11, wa.y, c1y), 0.0f));
            }
        }

        // ---- layer 2: g-blocks of 4 n-tiles; each LDSM feeds 4 MMAs ----
        uint32_t af0[32], af1[32];
        #pragma unroll
        for (int g2 = 0; g2 < 4; g2++) {
            float acc[8][4];   // [tile-in-block 0..3 x s 0..1 -> 2*ti+ss][4]
            #pragma unroll
            for (int i = 0; i < 8; i++)
                #pragma unroll
                for (int q = 0; q < 4; q++) acc[i][q] = 0.0f;

            #pragma unroll
            for (int ks = 0; ks < 8; ks++) {
                const uint32_t swb = (((uint32_t)(2 * ks) + cB) ^ n7B) * 16u;
                uint32_t bqA[4], bqB[4];
                LDSM_X4(bqA, sb + OFF_W2 + rowB + (uint32_t)(2*g2)     * 4096u + swb);
                LDSM_X4(bqB, sb + OFF_W2 + rowB + (uint32_t)(2*g2 + 1) * 4096u + swb);
                mma_bf16(acc[0], &aIn0[4*ks], bqA[0], bqA[1]);
                mma_bf16(acc[1], &aIn1[4*ks], bqA[0], bqA[1]);
                mma_bf16(acc[2], &aIn0[4*ks], bqA[2], bqA[3]);
                mma_bf16(acc[3], &aIn1[4*ks], bqA[2], bqA[3]);
                mma_bf16(acc[4], &aIn0[4*ks], bqB[0], bqB[1]);
                mma_bf16(acc[5], &aIn1[4*ks], bqB[0], bqB[1]);
                mma_bf16(acc[6], &aIn0[4*ks], bqB[2], bqB[3]);
                mma_bf16(acc[7], &aIn1[4*ks], bqB[2], bqB[3]);
            }
            // epilogue: relu(D+b2) -> L3 A-frags for tiles 4*g2..4*g2+3
            #pragma unroll
            for (int ti = 0; ti < 4; ti++) {
                int t = 4 * g2 + ti;
                int n0 = 8 * t + kq;
                float2 b2v = *(const float2*)&sB2[n0];
                const float* A0 = acc[2 * ti];
                const float* A1 = acc[2 * ti + 1];
                af0[2*t]     = pack_bf16(fmaxf(A0[0] + b2v.x, 0.0f), fmaxf(A0[1] + b2v.y, 0.0f));
                af0[2*t + 1] = pack_bf16(fmaxf(A0[2] + b2v.x, 0.0f), fmaxf(A0[3] + b2v.y, 0.0f));
                af1[2*t]     = pack_bf16(fmaxf(A1[0] + b2v.x, 0.0f), fmaxf(A1[1] + b2v.y, 0.0f));
                af1[2*t + 1] = pack_bf16(fmaxf(A1[2] + b2v.x, 0.0f), fmaxf(A1[3] + b2v.y, 0.0f));
            }
        }

        // ---- layer 3 + fused layer 4 partials ----
        float p00 = 0.0f, p01 = 0.0f, p10 = 0.0f, p11 = 0.0f;
        #pragma unroll
        for (int g2 = 0; g2 < 4; g2++) {
            float acc[8][4];
            #pragma unroll
            for (int i = 0; i < 8; i++)
                #pragma unroll
                for (int q = 0; q < 4; q++) acc[i][q] = 0.0f;

            #pragma unroll
            for (int ks = 0; ks < 8; ks++) {
                const uint32_t swb = (((uint32_t)(2 * ks) + cB) ^ n7B) * 16u;
                uint32_t bqA[4], bqB[4];
                LDSM_X4(bqA, sb + OFF_W3 + rowB + (uint32_t)(2*g2)     * 4096u + swb);
                LDSM_X4(bqB, sb + OFF_W3 + rowB + (uint32_t)(2*g2 + 1) * 4096u + swb);
                mma_bf16(acc[0], &af0[4*ks], bqA[0], bqA[1]);
                mma_bf16(acc[1], &af1[4*ks], bqA[0], bqA[1]);
                mma_bf16(acc[2], &af0[4*ks], bqA[2], bqA[3]);
                mma_bf16(acc[3], &af1[4*ks], bqA[2], bqA[3]);
                mma_bf16(acc[4], &af0[4*ks], bqB[0], bqB[1]);
                mma_bf16(acc[5], &af1[4*ks], bqB[0], bqB[1]);
                mma_bf16(acc[6], &af0[4*ks], bqB[2], bqB[3]);
                mma_bf16(acc[7], &af1[4*ks], bqB[2], bqB[3]);
            }
            // layer 4 partials for tiles 4*g2..4*g2+3
            #pragma unroll
            for (int ti = 0; ti < 4; ti++) {
                int t = 4 * g2 + ti;
                int n0 = 8 * t + kq;
                float2 b3v = *(const float2*)&sB3[n0];
                float2 w4v = *(const float2*)&sW4[n0];
                const float* A0 = acc[2 * ti];
                const float* A1 = acc[2 * ti + 1];
                p00 = fmaf(fmaxf(A0[0] + b3v.x, 0.0f), w4v.x, p00);
                p00 = fmaf(fmaxf(A0[1] + b3v.y, 0.0f), w4v.y, p00);
                p01 = fmaf(fmaxf(A0[2] + b3v.x, 0.0f), w4v.x, p01);
                p01 = fmaf(fmaxf(A0[3] + b3v.y, 0.0f), w4v.y, p01);
                p10 = fmaf(fmaxf(A1[0] + b3v.x, 0.0f), w4v.x, p10);
                p10 = fmaf(fmaxf(A1[1] + b3v.y, 0.0f), w4v.y, p10);
                p11 = fmaf(fmaxf(A1[2] + b3v.x, 0.0f), w4v.x, p11);
                p11 = fmaf(fmaxf(A1[3] + b3v.y, 0.0f), w4v.y, p11);
            }
        }

        // quad shfl-reduce (lanes of a quad share the same row)
        p00 += __shfl_xor_sync(0xFFFFFFFFu, p00, 1);
        p00 += __shfl_xor_sync(0xFFFFFFFFu, p00, 2);
        p01 += __shfl_xor_sync(0xFFFFFFFFu, p01, 1);
        p01 += __shfl_xor_sync(0xFFFFFFFFu, p01, 2);
        p10 += __shfl_xor_sync(0xFFFFFFFFu, p10, 1);
        p10 += __shfl_xor_sync(0xFFFFFFFFu, p10, 2);
        p11 += __shfl_xor_sync(0xFFFFFFFFu, p11, 1);
        p11 += __shfl_xor_sync(0xFFFFFFFFu, p11, 2);

        const float ccw0 = sCCW[s0], ccw1 = sCCW[s1];
        float v;
        v = p00 + b4v; z0 = fmaf(ccw0, ((v > 0.0f) ? v : expm1f(v)) + 1.0f, z0);
        v = p01 + b4v; z1 = fmaf(ccw0, ((v > 0.0f) ? v : expm1f(v)) + 1.0f, z1);
        v = p10 + b4v; z0 = fmaf(ccw1, ((v > 0.0f) ? v : expm1f(v)) + 1.0f, z0);
        v = p11 + b4v; z1 = fmaf(ccw1, ((v > 0.0f) ? v : expm1f(v)) + 1.0f, z1);
    }

    if ((lane & 3) == 0) {
        out[bbase + r0] = fmaf(z0, 0.5f * xm0, hm0);
        out[bbase + r1] = fmaf(z1, 0.5f * xm1, hm1);
    }
}

extern "C" void kernel_launch(void* const* d_in, const int* in_sizes, int n_in,
                              void* d_out, int out_size) {
    const float* x  = (const float*)d_in[0];
    const float* h  = (const float*)d_in[1];
    const float* w1 = (const float*)d_in[2];
    const float* b1 = (const float*)d_in[3];
    const float* w2 = (const float*)d_in[4];
    const float* b2 = (const float*)d_in[5];
    const float* w3 = (const float*)d_in[6];
    const float* b3 = (const float*)d_in[7];
    const float* w4 = (const float*)d_in[8];
    const float* b4 = (const float*)d_in[9];
    float* out = (float*)d_out;

    static int attr_set = 0;
    if (!attr_set) {
        cudaFuncSetAttribute(monnn_kernel,
                             cudaFuncAttributeMaxDynamicSharedMemorySize, SMEM_TOTAL);
        attr_set = 1;
    }
    monnn_kernel<<<BATCH / TM, NTHR, SMEM_TOTAL>>>(x, h, w1, b1, w2, b2, w3, b3, w4, b4, out);
}